// round 2
// baseline (speedup 1.0000x reference)
#include <cuda_runtime.h>
#include <math.h>

#define I_DIM 384
#define J_DIM 384
#define C_DIM 128
#define H_DIM 4
#define D_DIM 32
#define ROWS (I_DIM * J_DIM)          // 147456
#define LN_EPS 1e-5f
#define INF_V 1.0e9f

// ---------------- scratch (allocation-free rule: __device__ globals) --------
__device__ float g_xn[ROWS * C_DIM];   // layernormed x       [I,J,C]
__device__ float g_tri[ROWS * H_DIM];  // triangle bias       [I,J,H] (= tri[h,i,j])
__device__ float g_q[ROWS * C_DIM];    // q (pre-scaled)      [I,J,H,D]
__device__ float g_k[ROWS * C_DIM];    // k                   [I,J,H,D]
__device__ float g_v[ROWS * C_DIM];    // v                   [I,J,H,D]
__device__ float g_g[ROWS * C_DIM];    // sigmoid gate        [I,J,H,D]
__device__ float g_o[ROWS * C_DIM];    // gated attention out [I,J,H,D]

// ---------------- Kernel 1: LayerNorm + triangle-bias projection -----------
// one block per (i,j) row, 128 threads (one per channel)
__global__ __launch_bounds__(128) void ln_tri_kernel(
    const float* __restrict__ x,
    const float* __restrict__ ln_g,
    const float* __restrict__ ln_b,
    const float* __restrict__ w_tri)
{
    int row = blockIdx.x;
    int c   = threadIdx.x;
    int wid = c >> 5, lid = c & 31;

    float v = x[(size_t)row * C_DIM + c];

    // mean
    float s = v;
    #pragma unroll
    for (int o = 16; o; o >>= 1) s += __shfl_xor_sync(0xffffffffu, s, o);
    __shared__ float sm[4];
    if (lid == 0) sm[wid] = s;
    __syncthreads();
    float mean = (sm[0] + sm[1] + sm[2] + sm[3]) * (1.0f / C_DIM);

    // var
    float d  = v - mean;
    float s2 = d * d;
    #pragma unroll
    for (int o = 16; o; o >>= 1) s2 += __shfl_xor_sync(0xffffffffu, s2, o);
    __shared__ float sm2[4];
    if (lid == 0) sm2[wid] = s2;
    __syncthreads();
    float var = (sm2[0] + sm2[1] + sm2[2] + sm2[3]) * (1.0f / C_DIM);

    float xn = d * rsqrtf(var + LN_EPS) * ln_g[c] + ln_b[c];
    g_xn[(size_t)row * C_DIM + c] = xn;

    // triangle bias: tri[h] = sum_c xn[c] * w_tri[c,h]   (w_tri is [C,H] row-major)
    float p0 = xn * w_tri[c * 4 + 0];
    float p1 = xn * w_tri[c * 4 + 1];
    float p2 = xn * w_tri[c * 4 + 2];
    float p3 = xn * w_tri[c * 4 + 3];
    #pragma unroll
    for (int o = 16; o; o >>= 1) {
        p0 += __shfl_xor_sync(0xffffffffu, p0, o);
        p1 += __shfl_xor_sync(0xffffffffu, p1, o);
        p2 += __shfl_xor_sync(0xffffffffu, p2, o);
        p3 += __shfl_xor_sync(0xffffffffu, p3, o);
    }
    __shared__ float smt[4][4];
    if (lid == 0) {
        smt[wid][0] = p0; smt[wid][1] = p1; smt[wid][2] = p2; smt[wid][3] = p3;
    }
    __syncthreads();
    if (c < 4) {
        g_tri[(size_t)row * 4 + c] =
            smt[0][c] + smt[1][c] + smt[2][c] + smt[3][c];
    }
}

// ---------------- Kernel 2: 4 projection GEMMs (q,k,v,g) --------------------
// C = A[147456,128] * W[128,128]; block = 64 rows x 128 cols, 256 threads,
// microtile 4x8. blockIdx.y selects which weight/output.
__global__ __launch_bounds__(256) void proj4_kernel(
    const float* __restrict__ wq, const float* __restrict__ wk,
    const float* __restrict__ wv, const float* __restrict__ wg,
    const float* __restrict__ bg)
{
    int m0 = blockIdx.x * 64;
    int y  = blockIdx.y;
    const float* W = (y == 0) ? wq : (y == 1) ? wk : (y == 2) ? wv : wg;
    float*       O = (y == 0) ? g_q : (y == 1) ? g_k : (y == 2) ? g_v : g_g;

    __shared__ float As[64][33];
    __shared__ float Bs[32][132];

    int tid = threadIdx.x;
    int ty = tid >> 4, tx = tid & 15;   // 16x16 thread grid
    float acc[4][8];
    #pragma unroll
    for (int r = 0; r < 4; r++)
        #pragma unroll
        for (int j = 0; j < 8; j++) acc[r][j] = 0.0f;

    for (int kt = 0; kt < 4; kt++) {
        #pragma unroll
        for (int i = 0; i < 8; i++) {
            int idx = tid + i * 256;
            int r = idx >> 5, k = idx & 31;
            As[r][k] = g_xn[(size_t)(m0 + r) * 128 + kt * 32 + k];
        }
        #pragma unroll
        for (int i = 0; i < 16; i++) {
            int idx = tid + i * 256;
            int k = idx >> 7, col = idx & 127;
            Bs[k][col] = W[(kt * 32 + k) * 128 + col];
        }
        __syncthreads();
        #pragma unroll
        for (int k = 0; k < 32; k++) {
            float a[4];
            #pragma unroll
            for (int r = 0; r < 4; r++) a[r] = As[ty * 4 + r][k];
            float4 b01 = *(const float4*)&Bs[k][tx * 8];
            float4 b23 = *(const float4*)&Bs[k][tx * 8 + 4];
            float b[8] = {b01.x, b01.y, b01.z, b01.w, b23.x, b23.y, b23.z, b23.w};
            #pragma unroll
            for (int r = 0; r < 4; r++)
                #pragma unroll
                for (int j = 0; j < 8; j++) acc[r][j] += a[r] * b[j];
        }
        __syncthreads();
    }

    const float scale = 0.17677669529663687f;   // 1/sqrt(32)
    #pragma unroll
    for (int r = 0; r < 4; r++) {
        #pragma unroll
        for (int j = 0; j < 8; j++) {
            int col = tx * 8 + j;
            float val = acc[r][j];
            if (y == 0) val *= scale;
            if (y == 3) val = 1.0f / (1.0f + __expf(-(val + bg[col])));
            O[(size_t)(m0 + ty * 4 + r) * 128 + col] = val;
        }
    }
}

// ---------------- Kernel 3: per-(row, head) attention -----------------------
// grid (I, H), 384 threads (one per query). K/V staged in dynamic smem.
// Online softmax with tri bias (L2-resident) and mask bias.
__global__ __launch_bounds__(384) void attn_kernel(const float* __restrict__ mask)
{
    extern __shared__ float sh[];
    float* Ksh = sh;                 // [384][32]
    float* Vsh = sh + 384 * 32;      // [384][32]
    float* mb  = sh + 2 * 384 * 32;  // [384]

    int i = blockIdx.x, h = blockIdx.y;
    int tid = threadIdx.x;
    size_t base = (size_t)i * J_DIM * C_DIM + (size_t)h * D_DIM; // (i, j=0, h, d=0)

    // cooperative K/V load, float4 granularity: 3072 float4 over 384 threads
    #pragma unroll
    for (int it = 0; it < 8; it++) {
        int idx = tid + it * 384;           // float4 index: j*8 + d4
        int j = idx >> 3, d4 = idx & 7;
        ((float4*)Ksh)[idx] = *(const float4*)&g_k[base + (size_t)j * 128 + d4 * 4];
        ((float4*)Vsh)[idx] = *(const float4*)&g_v[base + (size_t)j * 128 + d4 * 4];
    }
    mb[tid] = INF_V * (mask[(size_t)i * J_DIM + tid] - 1.0f);
    __syncthreads();

    int q = tid;
    float qv[32];
    #pragma unroll
    for (int d4 = 0; d4 < 8; d4++) {
        float4 t = *(const float4*)&g_q[(size_t)(i * J_DIM + q) * 128 + h * 32 + d4 * 4];
        qv[4 * d4 + 0] = t.x; qv[4 * d4 + 1] = t.y;
        qv[4 * d4 + 2] = t.z; qv[4 * d4 + 3] = t.w;
    }

    const float* triP = g_tri + (size_t)q * J_DIM * 4 + h;  // tri[h, q, k], stride 4 over k

    float m = -1e30f, l = 0.0f;
    float o[32];
    #pragma unroll
    for (int d = 0; d < 32; d++) o[d] = 0.0f;

    float tnext = triP[0];
    for (int k = 0; k < J_DIM; k++) {
        float tb = tnext;
        if (k < J_DIM - 1) tnext = triP[(k + 1) * 4];       // prefetch next tri bias

        const float* kr = Ksh + k * 32;
        float dot = 0.0f;
        #pragma unroll
        for (int d = 0; d < 32; d++) dot += qv[d] * kr[d];

        float logit = dot + tb + mb[k];
        float nm   = fmaxf(m, logit);
        float corr = __expf(m - nm);
        float p    = __expf(logit - nm);
        l = l * corr + p;
        const float* vr = Vsh + k * 32;
        #pragma unroll
        for (int d = 0; d < 32; d++) o[d] = o[d] * corr + p * vr[d];
        m = nm;
    }

    float inv = 1.0f / l;
    size_t orow = (size_t)(i * J_DIM + q) * 128 + (size_t)h * 32;
    #pragma unroll
    for (int d = 0; d < 32; d++) {
        g_o[orow + d] = o[d] * inv * g_g[orow + d];
    }
}

// ---------------- Kernel 4: output projection + bias ------------------------
__global__ __launch_bounds__(256) void out_kernel(
    const float* __restrict__ wo, const float* __restrict__ bo,
    float* __restrict__ out)
{
    int m0 = blockIdx.x * 64;
    __shared__ float As[64][33];
    __shared__ float Bs[32][132];

    int tid = threadIdx.x;
    int ty = tid >> 4, tx = tid & 15;
    float acc[4][8];
    #pragma unroll
    for (int r = 0; r < 4; r++)
        #pragma unroll
        for (int j = 0; j < 8; j++) acc[r][j] = 0.0f;

    for (int kt = 0; kt < 4; kt++) {
        #pragma unroll
        for (int i = 0; i < 8; i++) {
            int idx = tid + i * 256;
            int r = idx >> 5, k = idx & 31;
            As[r][k] = g_o[(size_t)(m0 + r) * 128 + kt * 32 + k];
        }
        #pragma unroll
        for (int i = 0; i < 16; i++) {
            int idx = tid + i * 256;
            int k = idx >> 7, col = idx & 127;
            Bs[k][col] = wo[(kt * 32 + k) * 128 + col];
        }
        __syncthreads();
        #pragma unroll
        for (int k = 0; k < 32; k++) {
            float a[4];
            #pragma unroll
            for (int r = 0; r < 4; r++) a[r] = As[ty * 4 + r][k];
            float4 b01 = *(const float4*)&Bs[k][tx * 8];
            float4 b23 = *(const float4*)&Bs[k][tx * 8 + 4];
            float b[8] = {b01.x, b01.y, b01.z, b01.w, b23.x, b23.y, b23.z, b23.w};
            #pragma unroll
            for (int r = 0; r < 4; r++)
                #pragma unroll
                for (int j = 0; j < 8; j++) acc[r][j] += a[r] * b[j];
        }
        __syncthreads();
    }

    #pragma unroll
    for (int r = 0; r < 4; r++) {
        #pragma unroll
        for (int j = 0; j < 8; j++) {
            int col = tx * 8 + j;
            out[(size_t)(m0 + ty * 4 + r) * 128 + col] = acc[r][j] + bo[col];
        }
    }
}

// ---------------- launch ----------------------------------------------------
extern "C" void kernel_launch(void* const* d_in, const int* in_sizes, int n_in,
                              void* d_out, int out_size)
{
    const float* x     = (const float*)d_in[0];
    const float* mask  = (const float*)d_in[1];
    const float* ln_g  = (const float*)d_in[2];
    const float* ln_b  = (const float*)d_in[3];
    const float* w_tri = (const float*)d_in[4];
    const float* wq    = (const float*)d_in[5];
    const float* wk    = (const float*)d_in[6];
    const float* wv    = (const float*)d_in[7];
    const float* wg    = (const float*)d_in[8];
    const float* bg    = (const float*)d_in[9];
    const float* wo    = (const float*)d_in[10];
    const float* bo    = (const float*)d_in[11];
    float* out = (float*)d_out;

    const int SMEM_ATTN = (2 * 384 * 32 + 384) * (int)sizeof(float);  // 99840 B
    cudaFuncSetAttribute(attn_kernel,
                         cudaFuncAttributeMaxDynamicSharedMemorySize, SMEM_ATTN);

    ln_tri_kernel<<<ROWS, 128>>>(x, ln_g, ln_b, w_tri);
    proj4_kernel<<<dim3(ROWS / 64, 4), 256>>>(wq, wk, wv, wg, bg);
    attn_kernel<<<dim3(I_DIM, H_DIM), 384, SMEM_ATTN>>>(mask);
    out_kernel<<<ROWS / 64, 256>>>(wo, bo, out);
}

// round 3
// speedup vs baseline: 1.7008x; 1.7008x over previous
#include <cuda_runtime.h>
#include <math.h>

#define I_DIM 384
#define J_DIM 384
#define C_DIM 128
#define H_DIM 4
#define D_DIM 32
#define ROWS (I_DIM * J_DIM)          // 147456
#define LN_EPS 1e-5f
#define INF_V 1.0e9f

// ---------------- scratch (allocation-free rule: __device__ globals) --------
__device__ float g_xn[ROWS * C_DIM];   // layernormed x       [I,J,C]
__device__ float g_tri[H_DIM * ROWS];  // triangle bias       [H][I*J]  (tri[h][q*384+k])
__device__ float g_q[ROWS * C_DIM];    // q (pre-scaled)      [I,J,H,D]
__device__ float g_k[ROWS * C_DIM];    // k                   [I,J,H,D]
__device__ float g_v[ROWS * C_DIM];    // v                   [I,J,H,D]
__device__ float g_g[ROWS * C_DIM];    // sigmoid gate        [I,J,H,D]
__device__ float g_o[ROWS * C_DIM];    // gated attention out [I,J,H,D]

// ---------------- Kernel 1: LayerNorm + triangle-bias projection -----------
__global__ __launch_bounds__(128) void ln_tri_kernel(
    const float* __restrict__ x,
    const float* __restrict__ ln_g,
    const float* __restrict__ ln_b,
    const float* __restrict__ w_tri)
{
    int row = blockIdx.x;
    int c   = threadIdx.x;
    int wid = c >> 5, lid = c & 31;

    float v = x[(size_t)row * C_DIM + c];

    float s = v;
    #pragma unroll
    for (int o = 16; o; o >>= 1) s += __shfl_xor_sync(0xffffffffu, s, o);
    __shared__ float sm[4];
    if (lid == 0) sm[wid] = s;
    __syncthreads();
    float mean = (sm[0] + sm[1] + sm[2] + sm[3]) * (1.0f / C_DIM);

    float d  = v - mean;
    float s2 = d * d;
    #pragma unroll
    for (int o = 16; o; o >>= 1) s2 += __shfl_xor_sync(0xffffffffu, s2, o);
    __shared__ float sm2[4];
    if (lid == 0) sm2[wid] = s2;
    __syncthreads();
    float var = (sm2[0] + sm2[1] + sm2[2] + sm2[3]) * (1.0f / C_DIM);

    float xn = d * rsqrtf(var + LN_EPS) * ln_g[c] + ln_b[c];
    g_xn[(size_t)row * C_DIM + c] = xn;

    float p0 = xn * w_tri[c * 4 + 0];
    float p1 = xn * w_tri[c * 4 + 1];
    float p2 = xn * w_tri[c * 4 + 2];
    float p3 = xn * w_tri[c * 4 + 3];
    #pragma unroll
    for (int o = 16; o; o >>= 1) {
        p0 += __shfl_xor_sync(0xffffffffu, p0, o);
        p1 += __shfl_xor_sync(0xffffffffu, p1, o);
        p2 += __shfl_xor_sync(0xffffffffu, p2, o);
        p3 += __shfl_xor_sync(0xffffffffu, p3, o);
    }
    __shared__ float smt[4][4];
    if (lid == 0) {
        smt[wid][0] = p0; smt[wid][1] = p1; smt[wid][2] = p2; smt[wid][3] = p3;
    }
    __syncthreads();
    if (c < 4) {
        // layout [H][I*J] so attention streams k contiguously
        g_tri[(size_t)c * ROWS + row] =
            smt[0][c] + smt[1][c] + smt[2][c] + smt[3][c];
    }
}

// ---------------- GEMM tile: 128x128, 256 threads, 8x8 microtile ------------
// As flat [128*32], Bs flat [32*128], all staging via float4.
#define GEMM_BODY(A_PTR, W_PTR)                                                \
    __shared__ float As[128 * 32];                                             \
    __shared__ float Bs[32 * 128];                                             \
    int tid = threadIdx.x;                                                     \
    int ty = tid >> 4, tx = tid & 15;                                          \
    float acc[8][8];                                                           \
    _Pragma("unroll")                                                          \
    for (int r = 0; r < 8; r++)                                                \
        _Pragma("unroll")                                                      \
        for (int j = 0; j < 8; j++) acc[r][j] = 0.0f;                          \
    const float4* A4 = (const float4*)(A_PTR);                                 \
    const float4* W4 = (const float4*)(W_PTR);                                 \
    for (int kt = 0; kt < 4; kt++) {                                           \
        _Pragma("unroll")                                                      \
        for (int i = 0; i < 4; i++) {                                          \
            int idx = tid + i * 256;      /* 0..1023 */                        \
            int r = idx >> 3, kq = idx & 7;                                    \
            ((float4*)As)[idx] = A4[(size_t)(m0 + r) * 32 + kt * 8 + kq];      \
        }                                                                      \
        _Pragma("unroll")                                                      \
        for (int i = 0; i < 4; i++) {                                          \
            int idx = tid + i * 256;                                           \
            int k = idx >> 5, cq = idx & 31;                                   \
            ((float4*)Bs)[idx] = W4[(size_t)(kt * 32 + k) * 32 + cq];          \
        }                                                                      \
        __syncthreads();                                                       \
        _Pragma("unroll")                                                      \
        for (int k = 0; k < 32; k++) {                                         \
            float a[8];                                                        \
            _Pragma("unroll")                                                  \
            for (int r = 0; r < 8; r++) a[r] = As[(ty * 8 + r) * 32 + k];      \
            float4 b01 = *(const float4*)&Bs[k * 128 + tx * 8];                \
            float4 b23 = *(const float4*)&Bs[k * 128 + tx * 8 + 4];            \
            float b[8] = {b01.x, b01.y, b01.z, b01.w,                          \
                          b23.x, b23.y, b23.z, b23.w};                         \
            _Pragma("unroll")                                                  \
            for (int r = 0; r < 8; r++)                                        \
                _Pragma("unroll")                                              \
                for (int j = 0; j < 8; j++) acc[r][j] += a[r] * b[j];          \
        }                                                                      \
        __syncthreads();                                                       \
    }

// ---------------- Kernel 2: 4 projection GEMMs (q,k,v,g) --------------------
__global__ __launch_bounds__(256) void proj4_kernel(
    const float* __restrict__ wq, const float* __restrict__ wk,
    const float* __restrict__ wv, const float* __restrict__ wg,
    const float* __restrict__ bg)
{
    int m0 = blockIdx.x * 128;
    int y  = blockIdx.y;
    const float* W = (y == 0) ? wq : (y == 1) ? wk : (y == 2) ? wv : wg;
    float*       O = (y == 0) ? g_q : (y == 1) ? g_k : (y == 2) ? g_v : g_g;

    GEMM_BODY(g_xn, W)

    const float scale = 0.17677669529663687f;   // 1/sqrt(32)
    #pragma unroll
    for (int r = 0; r < 8; r++) {
        float4 v0, v1;
        float tmp[8];
        #pragma unroll
        for (int j = 0; j < 8; j++) {
            int col = tx * 8 + j;
            float val = acc[r][j];
            if (y == 0) val *= scale;
            if (y == 3) val = 1.0f / (1.0f + __expf(-(val + bg[col])));
            tmp[j] = val;
        }
        v0 = make_float4(tmp[0], tmp[1], tmp[2], tmp[3]);
        v1 = make_float4(tmp[4], tmp[5], tmp[6], tmp[7]);
        float4* orow = (float4*)&O[(size_t)(m0 + ty * 8 + r) * 128 + tx * 8];
        orow[0] = v0; orow[1] = v1;
    }
}

// ---------------- Kernel 3: attention, 192 thr, 2 queries/thread ------------
__global__ __launch_bounds__(192) void attn_kernel(const float* __restrict__ mask)
{
    extern __shared__ float sh[];
    float* Ksh = sh;                 // [384][32]
    float* Vsh = sh + 384 * 32;      // [384][32]
    float* mb  = sh + 2 * 384 * 32;  // [384]

    int i = blockIdx.x, h = blockIdx.y;
    int tid = threadIdx.x;
    size_t base4 = (size_t)i * J_DIM * 32 + (size_t)h * 8;  // float4 units

    const float4* K4g = (const float4*)g_k;
    const float4* V4g = (const float4*)g_v;
    #pragma unroll
    for (int it = 0; it < 16; it++) {
        int idx = tid + it * 192;           // float4 index: j*8 + d4
        int j = idx >> 3, d4 = idx & 7;
        ((float4*)Ksh)[idx] = K4g[base4 + (size_t)j * 32 + d4];
        ((float4*)Vsh)[idx] = V4g[base4 + (size_t)j * 32 + d4];
    }
    for (int t = tid; t < 384; t += 192)
        mb[t] = INF_V * (mask[(size_t)i * J_DIM + t] - 1.0f);
    __syncthreads();

    int q0 = tid, q1 = tid + 192;

    float q0v[32], q1v[32];
    {
        const float4* qp0 = (const float4*)&g_q[(size_t)(i * J_DIM + q0) * 128 + h * 32];
        const float4* qp1 = (const float4*)&g_q[(size_t)(i * J_DIM + q1) * 128 + h * 32];
        #pragma unroll
        for (int d4 = 0; d4 < 8; d4++) {
            float4 a = qp0[d4], b = qp1[d4];
            q0v[4*d4+0]=a.x; q0v[4*d4+1]=a.y; q0v[4*d4+2]=a.z; q0v[4*d4+3]=a.w;
            q1v[4*d4+0]=b.x; q1v[4*d4+1]=b.y; q1v[4*d4+2]=b.z; q1v[4*d4+3]=b.w;
        }
    }

    const float4* tp0 = (const float4*)(g_tri + (size_t)h * ROWS + (size_t)q0 * J_DIM);
    const float4* tp1 = (const float4*)(g_tri + (size_t)h * ROWS + (size_t)q1 * J_DIM);

    float m0 = -1e30f, m1 = -1e30f, l0 = 0.0f, l1 = 0.0f;
    float o0[32], o1[32];
    #pragma unroll
    for (int d = 0; d < 32; d++) { o0[d] = 0.0f; o1[d] = 0.0f; }

    #pragma unroll 1
    for (int kb = 0; kb < 96; kb++) {
        float4 t0 = tp0[kb];
        float4 t1 = tp1[kb];
        float tb0a[4] = {t0.x, t0.y, t0.z, t0.w};
        float tb1a[4] = {t1.x, t1.y, t1.z, t1.w};
        #pragma unroll
        for (int u = 0; u < 4; u++) {
            int k = kb * 4 + u;
            const float4* kr = (const float4*)(Ksh + k * 32);
            float dot0 = 0.0f, dot1 = 0.0f;
            #pragma unroll
            for (int d4 = 0; d4 < 8; d4++) {
                float4 kk = kr[d4];
                dot0 = fmaf(q0v[4*d4+0], kk.x, dot0);
                dot0 = fmaf(q0v[4*d4+1], kk.y, dot0);
                dot0 = fmaf(q0v[4*d4+2], kk.z, dot0);
                dot0 = fmaf(q0v[4*d4+3], kk.w, dot0);
                dot1 = fmaf(q1v[4*d4+0], kk.x, dot1);
                dot1 = fmaf(q1v[4*d4+1], kk.y, dot1);
                dot1 = fmaf(q1v[4*d4+2], kk.z, dot1);
                dot1 = fmaf(q1v[4*d4+3], kk.w, dot1);
            }
            float mbk = mb[k];
            float lg0 = dot0 + tb0a[u] + mbk;
            float lg1 = dot1 + tb1a[u] + mbk;

            float nm0 = fmaxf(m0, lg0);
            float nm1 = fmaxf(m1, lg1);
            float p0 = __expf(lg0 - nm0);
            float p1 = __expf(lg1 - nm1);
            if (nm0 > m0) {                   // rare after warm-up
                float c = __expf(m0 - nm0);
                l0 *= c;
                #pragma unroll
                for (int d = 0; d < 32; d++) o0[d] *= c;
                m0 = nm0;
            }
            if (nm1 > m1) {
                float c = __expf(m1 - nm1);
                l1 *= c;
                #pragma unroll
                for (int d = 0; d < 32; d++) o1[d] *= c;
                m1 = nm1;
            }
            l0 += p0; l1 += p1;

            const float4* vr = (const float4*)(Vsh + k * 32);
            #pragma unroll
            for (int d4 = 0; d4 < 8; d4++) {
                float4 vv = vr[d4];
                o0[4*d4+0] = fmaf(p0, vv.x, o0[4*d4+0]);
                o0[4*d4+1] = fmaf(p0, vv.y, o0[4*d4+1]);
                o0[4*d4+2] = fmaf(p0, vv.z, o0[4*d4+2]);
                o0[4*d4+3] = fmaf(p0, vv.w, o0[4*d4+3]);
                o1[4*d4+0] = fmaf(p1, vv.x, o1[4*d4+0]);
                o1[4*d4+1] = fmaf(p1, vv.y, o1[4*d4+1]);
                o1[4*d4+2] = fmaf(p1, vv.z, o1[4*d4+2]);
                o1[4*d4+3] = fmaf(p1, vv.w, o1[4*d4+3]);
            }
        }
    }

    float inv0 = 1.0f / l0;
    float inv1 = 1.0f / l1;
    size_t r0 = (size_t)(i * J_DIM + q0) * 32 + (size_t)h * 8;  // float4 units
    size_t r1 = (size_t)(i * J_DIM + q1) * 32 + (size_t)h * 8;
    const float4* G4 = (const float4*)g_g;
    float4* O4 = (float4*)g_o;
    #pragma unroll
    for (int d4 = 0; d4 < 8; d4++) {
        float4 ga = G4[r0 + d4];
        float4 gb = G4[r1 + d4];
        O4[r0 + d4] = make_float4(o0[4*d4+0]*inv0*ga.x, o0[4*d4+1]*inv0*ga.y,
                                  o0[4*d4+2]*inv0*ga.z, o0[4*d4+3]*inv0*ga.w);
        O4[r1 + d4] = make_float4(o1[4*d4+0]*inv1*gb.x, o1[4*d4+1]*inv1*gb.y,
                                  o1[4*d4+2]*inv1*gb.z, o1[4*d4+3]*inv1*gb.w);
    }
}

// ---------------- Kernel 4: output projection + bias ------------------------
__global__ __launch_bounds__(256) void out_kernel(
    const float* __restrict__ wo, const float* __restrict__ bo,
    float* __restrict__ out)
{
    int m0 = blockIdx.x * 128;

    GEMM_BODY(g_o, wo)

    #pragma unroll
    for (int r = 0; r < 8; r++) {
        float tmp[8];
        #pragma unroll
        for (int j = 0; j < 8; j++) tmp[j] = acc[r][j] + bo[tx * 8 + j];
        float4* orow = (float4*)&out[(size_t)(m0 + ty * 8 + r) * 128 + tx * 8];
        orow[0] = make_float4(tmp[0], tmp[1], tmp[2], tmp[3]);
        orow[1] = make_float4(tmp[4], tmp[5], tmp[6], tmp[7]);
    }
}

// ---------------- launch ----------------------------------------------------
extern "C" void kernel_launch(void* const* d_in, const int* in_sizes, int n_in,
                              void* d_out, int out_size)
{
    const float* x     = (const float*)d_in[0];
    const float* mask  = (const float*)d_in[1];
    const float* ln_g  = (const float*)d_in[2];
    const float* ln_b  = (const float*)d_in[3];
    const float* w_tri = (const float*)d_in[4];
    const float* wq    = (const float*)d_in[5];
    const float* wk    = (const float*)d_in[6];
    const float* wv    = (const float*)d_in[7];
    const float* wg    = (const float*)d_in[8];
    const float* bg    = (const float*)d_in[9];
    const float* wo    = (const float*)d_in[10];
    const float* bo    = (const float*)d_in[11];
    float* out = (float*)d_out;

    const int SMEM_ATTN = (2 * 384 * 32 + 384) * (int)sizeof(float);  // 99840 B
    cudaFuncSetAttribute(attn_kernel,
                         cudaFuncAttributeMaxDynamicSharedMemorySize, SMEM_ATTN);

    ln_tri_kernel<<<ROWS, 128>>>(x, ln_g, ln_b, w_tri);
    proj4_kernel<<<dim3(ROWS / 128, 4), 256>>>(wq, wk, wv, wg, bg);
    attn_kernel<<<dim3(I_DIM, H_DIM), 192, SMEM_ATTN>>>(mask);
    out_kernel<<<ROWS / 128, 256>>>(wo, bo, out);
}

// round 4
// speedup vs baseline: 1.7910x; 1.0530x over previous
#include <cuda_runtime.h>
#include <math.h>

#define I_DIM 384
#define J_DIM 384
#define C_DIM 128
#define H_DIM 4
#define D_DIM 32
#define ROWS (I_DIM * J_DIM)          // 147456
#define LN_EPS 1e-5f
#define INF_V 1.0e9f

// ---------------- scratch (allocation-free rule: __device__ globals) --------
__device__ float g_xn[ROWS * C_DIM];   // layernormed x       [I,J,C]
__device__ float g_tri[H_DIM * ROWS];  // triangle bias       [H][I*J]  (tri[h][q*384+k])
__device__ float g_q[ROWS * C_DIM];    // q (pre-scaled)      [I,J,H,D]
__device__ float g_k[ROWS * C_DIM];    // k                   [I,J,H,D]
__device__ float g_v[ROWS * C_DIM];    // v                   [I,J,H,D]
__device__ float g_g[ROWS * C_DIM];    // sigmoid gate        [I,J,H,D]
__device__ float g_o[ROWS * C_DIM];    // gated attention out [I,J,H,D]

// ---------------- Kernel 1: LayerNorm + triangle-bias projection -----------
__global__ __launch_bounds__(128) void ln_tri_kernel(
    const float* __restrict__ x,
    const float* __restrict__ ln_g,
    const float* __restrict__ ln_b,
    const float* __restrict__ w_tri)
{
    int row = blockIdx.x;
    int c   = threadIdx.x;
    int wid = c >> 5, lid = c & 31;

    float v = x[(size_t)row * C_DIM + c];

    float s = v;
    #pragma unroll
    for (int o = 16; o; o >>= 1) s += __shfl_xor_sync(0xffffffffu, s, o);
    __shared__ float sm[4];
    if (lid == 0) sm[wid] = s;
    __syncthreads();
    float mean = (sm[0] + sm[1] + sm[2] + sm[3]) * (1.0f / C_DIM);

    float d  = v - mean;
    float s2 = d * d;
    #pragma unroll
    for (int o = 16; o; o >>= 1) s2 += __shfl_xor_sync(0xffffffffu, s2, o);
    __shared__ float sm2[4];
    if (lid == 0) sm2[wid] = s2;
    __syncthreads();
    float var = (sm2[0] + sm2[1] + sm2[2] + sm2[3]) * (1.0f / C_DIM);

    float xn = d * rsqrtf(var + LN_EPS) * ln_g[c] + ln_b[c];
    g_xn[(size_t)row * C_DIM + c] = xn;

    float p0 = xn * w_tri[c * 4 + 0];
    float p1 = xn * w_tri[c * 4 + 1];
    float p2 = xn * w_tri[c * 4 + 2];
    float p3 = xn * w_tri[c * 4 + 3];
    #pragma unroll
    for (int o = 16; o; o >>= 1) {
        p0 += __shfl_xor_sync(0xffffffffu, p0, o);
        p1 += __shfl_xor_sync(0xffffffffu, p1, o);
        p2 += __shfl_xor_sync(0xffffffffu, p2, o);
        p3 += __shfl_xor_sync(0xffffffffu, p3, o);
    }
    __shared__ float smt[4][4];
    if (lid == 0) {
        smt[wid][0] = p0; smt[wid][1] = p1; smt[wid][2] = p2; smt[wid][3] = p3;
    }
    __syncthreads();
    if (c < 4) {
        // layout [H][I*J] so attention streams k contiguously
        g_tri[(size_t)c * ROWS + row] =
            smt[0][c] + smt[1][c] + smt[2][c] + smt[3][c];
    }
}

// ---------------- GEMM tile: 128x128, 256 threads, 8x8 microtile ------------
// As flat [128*32], Bs flat [32*128], all staging via float4.
#define GEMM_BODY(A_PTR, W_PTR)                                                \
    __shared__ float As[128 * 32];                                             \
    __shared__ float Bs[32 * 128];                                             \
    int tid = threadIdx.x;                                                     \
    int ty = tid >> 4, tx = tid & 15;                                          \
    float acc[8][8];                                                           \
    _Pragma("unroll")                                                          \
    for (int r = 0; r < 8; r++)                                                \
        _Pragma("unroll")                                                      \
        for (int j = 0; j < 8; j++) acc[r][j] = 0.0f;                          \
    const float4* A4 = (const float4*)(A_PTR);                                 \
    const float4* W4 = (const float4*)(W_PTR);                                 \
    for (int kt = 0; kt < 4; kt++) {                                           \
        _Pragma("unroll")                                                      \
        for (int i = 0; i < 4; i++) {                                          \
            int idx = tid + i * 256;      /* 0..1023 */                        \
            int r = idx >> 3, kq = idx & 7;                                    \
            ((float4*)As)[idx] = A4[(size_t)(m0 + r) * 32 + kt * 8 + kq];      \
        }                                                                      \
        _Pragma("unroll")                                                      \
        for (int i = 0; i < 4; i++) {                                          \
            int idx = tid + i * 256;                                           \
            int k = idx >> 5, cq = idx & 31;                                   \
            ((float4*)Bs)[idx] = W4[(size_t)(kt * 32 + k) * 32 + cq];          \
        }                                                                      \
        __syncthreads();                                                       \
        _Pragma("unroll")                                                      \
        for (int k = 0; k < 32; k++) {                                         \
            float a[8];                                                        \
            _Pragma("unroll")                                                  \
            for (int r = 0; r < 8; r++) a[r] = As[(ty * 8 + r) * 32 + k];      \
            float4 b01 = *(const float4*)&Bs[k * 128 + tx * 8];                \
            float4 b23 = *(const float4*)&Bs[k * 128 + tx * 8 + 4];            \
            float b[8] = {b01.x, b01.y, b01.z, b01.w,                          \
                          b23.x, b23.y, b23.z, b23.w};                         \
            _Pragma("unroll")                                                  \
            for (int r = 0; r < 8; r++)                                        \
                _Pragma("unroll")                                              \
                for (int j = 0; j < 8; j++) acc[r][j] += a[r] * b[j];          \
        }                                                                      \
        __syncthreads();                                                       \
    }

// ---------------- Kernel 2: 4 projection GEMMs (q,k,v,g) --------------------
__global__ __launch_bounds__(256) void proj4_kernel(
    const float* __restrict__ wq, const float* __restrict__ wk,
    const float* __restrict__ wv, const float* __restrict__ wg,
    const float* __restrict__ bg)
{
    int m0 = blockIdx.x * 128;
    int y  = blockIdx.y;
    const float* W = (y == 0) ? wq : (y == 1) ? wk : (y == 2) ? wv : wg;
    float*       O = (y == 0) ? g_q : (y == 1) ? g_k : (y == 2) ? g_v : g_g;

    GEMM_BODY(g_xn, W)

    const float scale = 0.17677669529663687f;   // 1/sqrt(32)
    #pragma unroll
    for (int r = 0; r < 8; r++) {
        float4 v0, v1;
        float tmp[8];
        #pragma unroll
        for (int j = 0; j < 8; j++) {
            int col = tx * 8 + j;
            float val = acc[r][j];
            if (y == 0) val *= scale;
            if (y == 3) val = 1.0f / (1.0f + __expf(-(val + bg[col])));
            tmp[j] = val;
        }
        v0 = make_float4(tmp[0], tmp[1], tmp[2], tmp[3]);
        v1 = make_float4(tmp[4], tmp[5], tmp[6], tmp[7]);
        float4* orow = (float4*)&O[(size_t)(m0 + ty * 8 + r) * 128 + tx * 8];
        orow[0] = v0; orow[1] = v1;
    }
}

// ---------------- Kernel 3: attention, 192 thr, 2 queries/thread ------------
__global__ __launch_bounds__(192) void attn_kernel(const float* __restrict__ mask)
{
    extern __shared__ float sh[];
    float* Ksh = sh;                 // [384][32]
    float* Vsh = sh + 384 * 32;      // [384][32]
    float* mb  = sh + 2 * 384 * 32;  // [384]

    int i = blockIdx.x, h = blockIdx.y;
    int tid = threadIdx.x;
    size_t base4 = (size_t)i * J_DIM * 32 + (size_t)h * 8;  // float4 units

    const float4* K4g = (const float4*)g_k;
    const float4* V4g = (const float4*)g_v;
    #pragma unroll
    for (int it = 0; it < 16; it++) {
        int idx = tid + it * 192;           // float4 index: j*8 + d4
        int j = idx >> 3, d4 = idx & 7;
        ((float4*)Ksh)[idx] = K4g[base4 + (size_t)j * 32 + d4];
        ((float4*)Vsh)[idx] = V4g[base4 + (size_t)j * 32 + d4];
    }
    for (int t = tid; t < 384; t += 192)
        mb[t] = INF_V * (mask[(size_t)i * J_DIM + t] - 1.0f);
    __syncthreads();

    int q0 = tid, q1 = tid + 192;

    float q0v[32], q1v[32];
    {
        const float4* qp0 = (const float4*)&g_q[(size_t)(i * J_DIM + q0) * 128 + h * 32];
        const float4* qp1 = (const float4*)&g_q[(size_t)(i * J_DIM + q1) * 128 + h * 32];
        #pragma unroll
        for (int d4 = 0; d4 < 8; d4++) {
            float4 a = qp0[d4], b = qp1[d4];
            q0v[4*d4+0]=a.x; q0v[4*d4+1]=a.y; q0v[4*d4+2]=a.z; q0v[4*d4+3]=a.w;
            q1v[4*d4+0]=b.x; q1v[4*d4+1]=b.y; q1v[4*d4+2]=b.z; q1v[4*d4+3]=b.w;
        }
    }

    const float4* tp0 = (const float4*)(g_tri + (size_t)h * ROWS + (size_t)q0 * J_DIM);
    const float4* tp1 = (const float4*)(g_tri + (size_t)h * ROWS + (size_t)q1 * J_DIM);

    float m0 = -1e30f, m1 = -1e30f, l0 = 0.0f, l1 = 0.0f;
    float o0[32], o1[32];
    #pragma unroll
    for (int d = 0; d < 32; d++) { o0[d] = 0.0f; o1[d] = 0.0f; }

    #pragma unroll 1
    for (int kb = 0; kb < 96; kb++) {
        float4 t0 = tp0[kb];
        float4 t1 = tp1[kb];
        float tb0a[4] = {t0.x, t0.y, t0.z, t0.w};
        float tb1a[4] = {t1.x, t1.y, t1.z, t1.w};
        #pragma unroll
        for (int u = 0; u < 4; u++) {
            int k = kb * 4 + u;
            const float4* kr = (const float4*)(Ksh + k * 32);
            float dot0 = 0.0f, dot1 = 0.0f;
            #pragma unroll
            for (int d4 = 0; d4 < 8; d4++) {
                float4 kk = kr[d4];
                dot0 = fmaf(q0v[4*d4+0], kk.x, dot0);
                dot0 = fmaf(q0v[4*d4+1], kk.y, dot0);
                dot0 = fmaf(q0v[4*d4+2], kk.z, dot0);
                dot0 = fmaf(q0v[4*d4+3], kk.w, dot0);
                dot1 = fmaf(q1v[4*d4+0], kk.x, dot1);
                dot1 = fmaf(q1v[4*d4+1], kk.y, dot1);
                dot1 = fmaf(q1v[4*d4+2], kk.z, dot1);
                dot1 = fmaf(q1v[4*d4+3], kk.w, dot1);
            }
            float mbk = mb[k];
            float lg0 = dot0 + tb0a[u] + mbk;
            float lg1 = dot1 + tb1a[u] + mbk;

            float nm0 = fmaxf(m0, lg0);
            float nm1 = fmaxf(m1, lg1);
            float p0 = __expf(lg0 - nm0);
            float p1 = __expf(lg1 - nm1);
            if (nm0 > m0) {                   // rare after warm-up
                float c = __expf(m0 - nm0);
                l0 *= c;
                #pragma unroll
                for (int d = 0; d < 32; d++) o0[d] *= c;
                m0 = nm0;
            }
            if (nm1 > m1) {
                float c = __expf(m1 - nm1);
                l1 *= c;
                #pragma unroll
                for (int d = 0; d < 32; d++) o1[d] *= c;
                m1 = nm1;
            }
            l0 += p0; l1 += p1;

            const float4* vr = (const float4*)(Vsh + k * 32);
            #pragma unroll
            for (int d4 = 0; d4 < 8; d4++) {
                float4 vv = vr[d4];
                o0[4*d4+0] = fmaf(p0, vv.x, o0[4*d4+0]);
                o0[4*d4+1] = fmaf(p0, vv.y, o0[4*d4+1]);
                o0[4*d4+2] = fmaf(p0, vv.z, o0[4*d4+2]);
                o0[4*d4+3] = fmaf(p0, vv.w, o0[4*d4+3]);
                o1[4*d4+0] = fmaf(p1, vv.x, o1[4*d4+0]);
                o1[4*d4+1] = fmaf(p1, vv.y, o1[4*d4+1]);
                o1[4*d4+2] = fmaf(p1, vv.z, o1[4*d4+2]);
                o1[4*d4+3] = fmaf(p1, vv.w, o1[4*d4+3]);
            }
        }
    }

    float inv0 = 1.0f / l0;
    float inv1 = 1.0f / l1;
    size_t r0 = (size_t)(i * J_DIM + q0) * 32 + (size_t)h * 8;  // float4 units
    size_t r1 = (size_t)(i * J_DIM + q1) * 32 + (size_t)h * 8;
    const float4* G4 = (const float4*)g_g;
    float4* O4 = (float4*)g_o;
    #pragma unroll
    for (int d4 = 0; d4 < 8; d4++) {
        float4 ga = G4[r0 + d4];
        float4 gb = G4[r1 + d4];
        O4[r0 + d4] = make_float4(o0[4*d4+0]*inv0*ga.x, o0[4*d4+1]*inv0*ga.y,
                                  o0[4*d4+2]*inv0*ga.z, o0[4*d4+3]*inv0*ga.w);
        O4[r1 + d4] = make_float4(o1[4*d4+0]*inv1*gb.x, o1[4*d4+1]*inv1*gb.y,
                                  o1[4*d4+2]*inv1*gb.z, o1[4*d4+3]*inv1*gb.w);
    }
}

// ---------------- Kernel 4: output projection + bias ------------------------
__global__ __launch_bounds__(256) void out_kernel(
    const float* __restrict__ wo, const float* __restrict__ bo,
    float* __restrict__ out)
{
    int m0 = blockIdx.x * 128;

    GEMM_BODY(g_o, wo)

    #pragma unroll
    for (int r = 0; r < 8; r++) {
        float tmp[8];
        #pragma unroll
        for (int j = 0; j < 8; j++) tmp[j] = acc[r][j] + bo[tx * 8 + j];
        float4* orow = (float4*)&out[(size_t)(m0 + ty * 8 + r) * 128 + tx * 8];
        orow[0] = make_float4(tmp[0], tmp[1], tmp[2], tmp[3]);
        orow[1] = make_float4(tmp[4], tmp[5], tmp[6], tmp[7]);
    }
}

// ---------------- launch ----------------------------------------------------
extern "C" void kernel_launch(void* const* d_in, const int* in_sizes, int n_in,
                              void* d_out, int out_size)
{
    const float* x     = (const float*)d_in[0];
    const float* mask  = (const float*)d_in[1];
    const float* ln_g  = (const float*)d_in[2];
    const float* ln_b  = (const float*)d_in[3];
    const float* w_tri = (const float*)d_in[4];
    const float* wq    = (const float*)d_in[5];
    const float* wk    = (const float*)d_in[6];
    const float* wv    = (const float*)d_in[7];
    const float* wg    = (const float*)d_in[8];
    const float* bg    = (const float*)d_in[9];
    const float* wo    = (const float*)d_in[10];
    const float* bo    = (const float*)d_in[11];
    float* out = (float*)d_out;

    const int SMEM_ATTN = (2 * 384 * 32 + 384) * (int)sizeof(float);  // 99840 B
    cudaFuncSetAttribute(attn_kernel,
                         cudaFuncAttributeMaxDynamicSharedMemorySize, SMEM_ATTN);

    ln_tri_kernel<<<ROWS, 128>>>(x, ln_g, ln_b, w_tri);
    proj4_kernel<<<dim3(ROWS / 128, 4), 256>>>(wq, wk, wv, wg, bg);
    attn_kernel<<<dim3(I_DIM, H_DIM), 192, SMEM_ATTN>>>(mask);
    out_kernel<<<ROWS / 128, 256>>>(wo, bo, out);
}

// round 6
// speedup vs baseline: 4.1832x; 2.3356x over previous
#include <cuda_runtime.h>
#include <math.h>
#include <stdint.h>

#define I_DIM 384
#define J_DIM 384
#define C_DIM 128
#define H_DIM 4
#define ROWS (I_DIM * J_DIM)          // 147456
#define LN_EPS 1e-5f
#define LOG2E 1.4426950408889634f

// ---------------- scratch -----------------------------------------------
__device__ float g_xn[ROWS * C_DIM];
__device__ float g_tri[H_DIM * ROWS];   // [h][q*384+k], pre-scaled by LOG2E
__device__ float g_q[ROWS * C_DIM];     // pre-scaled by (1/sqrt(32))*LOG2E
__device__ float g_k[ROWS * C_DIM];
__device__ float g_v[ROWS * C_DIM];
__device__ float g_g[ROWS * C_DIM];
__device__ float g_o[ROWS * C_DIM];

// ---------------- helpers -----------------------------------------------
__device__ __forceinline__ uint32_t f2tf(float x) {
    uint32_t r; asm("cvt.rna.tf32.f32 %0, %1;" : "=r"(r) : "f"(x)); return r;
}
__device__ __forceinline__ float tf2f(float x) {       // tf32 bits kept in float
    return __uint_as_float(f2tf(x));
}
__device__ __forceinline__ float ex2(float x) {
    float r; asm("ex2.approx.ftz.f32 %0, %1;" : "=f"(r) : "f"(x)); return r;
}
__device__ __forceinline__ void mma8(float* c, const uint32_t* a,
                                     uint32_t b0, uint32_t b1) {
    asm volatile(
        "mma.sync.aligned.m16n8k8.row.col.f32.tf32.tf32.f32 "
        "{%0,%1,%2,%3},{%4,%5,%6,%7},{%8,%9},{%0,%1,%2,%3};"
        : "+f"(c[0]), "+f"(c[1]), "+f"(c[2]), "+f"(c[3])
        : "r"(a[0]), "r"(a[1]), "r"(a[2]), "r"(a[3]), "r"(b0), "r"(b1));
}
#define BITS(x) __float_as_uint(x)

// ---------------- Kernel 1: LN + tri (warp per row) ----------------------
__global__ __launch_bounds__(256) void ln_tri_kernel(
    const float* __restrict__ x, const float* __restrict__ ln_g,
    const float* __restrict__ ln_b, const float* __restrict__ w_tri)
{
    int row  = blockIdx.x * 8 + (threadIdx.x >> 5);
    int lane = threadIdx.x & 31;

    float4 v = ((const float4*)x)[(size_t)row * 32 + lane];
    float s = v.x + v.y + v.z + v.w;
    #pragma unroll
    for (int o = 16; o; o >>= 1) s += __shfl_xor_sync(~0u, s, o);
    float mean = s * (1.0f / 128.0f);

    float4 d = make_float4(v.x - mean, v.y - mean, v.z - mean, v.w - mean);
    float s2 = d.x*d.x + d.y*d.y + d.z*d.z + d.w*d.w;
    #pragma unroll
    for (int o = 16; o; o >>= 1) s2 += __shfl_xor_sync(~0u, s2, o);
    float rstd = rsqrtf(s2 * (1.0f / 128.0f) + LN_EPS);

    float4 gg = ((const float4*)ln_g)[lane];
    float4 bb = ((const float4*)ln_b)[lane];
    float4 xn;
    xn.x = d.x * rstd * gg.x + bb.x;
    xn.y = d.y * rstd * gg.y + bb.y;
    xn.z = d.z * rstd * gg.z + bb.z;
    xn.w = d.w * rstd * gg.w + bb.w;
    ((float4*)g_xn)[(size_t)row * 32 + lane] = xn;

    const float4* wt = (const float4*)w_tri;   // w_tri[c][0..3] is one float4
    float4 w0 = wt[lane*4+0], w1 = wt[lane*4+1], w2 = wt[lane*4+2], w3 = wt[lane*4+3];
    float p0 = xn.x*w0.x + xn.y*w1.x + xn.z*w2.x + xn.w*w3.x;
    float p1 = xn.x*w0.y + xn.y*w1.y + xn.z*w2.y + xn.w*w3.y;
    float p2 = xn.x*w0.z + xn.y*w1.z + xn.z*w2.z + xn.w*w3.z;
    float p3 = xn.x*w0.w + xn.y*w1.w + xn.z*w2.w + xn.w*w3.w;
    #pragma unroll
    for (int o = 16; o; o >>= 1) {
        p0 += __shfl_xor_sync(~0u, p0, o);
        p1 += __shfl_xor_sync(~0u, p1, o);
        p2 += __shfl_xor_sync(~0u, p2, o);
        p3 += __shfl_xor_sync(~0u, p3, o);
    }
    if (lane < 4) {
        float pv = (lane == 0) ? p0 : (lane == 1) ? p1 : (lane == 2) ? p2 : p3;
        g_tri[(size_t)lane * ROWS + row] = pv * LOG2E;
    }
}

// ---------------- Kernel 2: fused q/k/v/g projection (tf32 MMA) ----------
// 128x128 tile, 8 warps (4x2), warp tile 32x64, A staged once, 4 weights looped.
#define SA 132    // A smem row stride (floats): bank = lane -> conflict-free
#define SB 136    // B smem row stride: 136%32=8 -> conflict-free

__global__ __launch_bounds__(256) void proj_kernel(
    const float* __restrict__ wq, const float* __restrict__ wk,
    const float* __restrict__ wv, const float* __restrict__ wg,
    const float* __restrict__ bg)
{
    extern __shared__ float sh[];
    float* As = sh;                 // [128][SA]
    float* Bs = sh + 128 * SA;      // [128][SB]

    int m0 = blockIdx.x * 128;
    int tid = threadIdx.x, wid = tid >> 5, lane = tid & 31;
    int warpM = (wid >> 1) * 32, warpN = (wid & 1) * 64;
    int q4 = lane & 3, r8 = lane >> 2;

    const float4* A4 = (const float4*)g_xn + (size_t)m0 * 32;
    #pragma unroll
    for (int it = 0; it < 16; it++) {
        int idx = tid + it * 256;
        int rr = idx >> 5, c4 = idx & 31;
        float4 v = A4[rr * 32 + c4];
        float* dst = As + rr * SA + c4 * 4;
        dst[0] = tf2f(v.x); dst[1] = tf2f(v.y); dst[2] = tf2f(v.z); dst[3] = tf2f(v.w);
    }

    #pragma unroll 1
    for (int y = 0; y < 4; y++) {
        const float* W = (y == 0) ? wq : (y == 1) ? wk : (y == 2) ? wv : wg;
        float*       O = (y == 0) ? g_q : (y == 1) ? g_k : (y == 2) ? g_v : g_g;

        __syncthreads();           // covers A staging (y=0) / prior readers
        const float4* W4 = (const float4*)W;
        #pragma unroll
        for (int it = 0; it < 16; it++) {
            int idx = tid + it * 256;
            int kk = idx >> 5, c4 = idx & 31;
            float4 v = W4[idx];
            float* dst = Bs + kk * SB + c4 * 4;
            dst[0] = tf2f(v.x); dst[1] = tf2f(v.y); dst[2] = tf2f(v.z); dst[3] = tf2f(v.w);
        }
        __syncthreads();

        float acc[2][8][4];
        #pragma unroll
        for (int mt = 0; mt < 2; mt++)
            #pragma unroll
            for (int nt = 0; nt < 8; nt++)
                #pragma unroll
                for (int u = 0; u < 4; u++) acc[mt][nt][u] = 0.0f;

        #pragma unroll
        for (int ks = 0; ks < 16; ks++) {
            int k0 = ks * 8;
            uint32_t a[2][4];
            #pragma unroll
            for (int mt = 0; mt < 2; mt++) {
                int rb = warpM + mt * 16 + r8;
                a[mt][0] = BITS(As[rb * SA + k0 + q4]);
                a[mt][1] = BITS(As[(rb + 8) * SA + k0 + q4]);
                a[mt][2] = BITS(As[rb * SA + k0 + q4 + 4]);
                a[mt][3] = BITS(As[(rb + 8) * SA + k0 + q4 + 4]);
            }
            #pragma unroll
            for (int nt = 0; nt < 8; nt++) {
                int nb = warpN + nt * 8 + r8;
                uint32_t b0 = BITS(Bs[(k0 + q4) * SB + nb]);
                uint32_t b1 = BITS(Bs[(k0 + q4 + 4) * SB + nb]);
                mma8(acc[0][nt], a[0], b0, b1);
                mma8(acc[1][nt], a[1], b0, b1);
            }
        }

        const float qscale = 0.17677669529663687f * LOG2E;
        #pragma unroll
        for (int mt = 0; mt < 2; mt++) {
            int row0 = m0 + warpM + mt * 16 + r8;
            #pragma unroll
            for (int nt = 0; nt < 8; nt++) {
                int col = warpN + nt * 8 + 2 * q4;
                float v0 = acc[mt][nt][0], v1 = acc[mt][nt][1];
                float v2 = acc[mt][nt][2], v3 = acc[mt][nt][3];
                if (y == 0) { v0 *= qscale; v1 *= qscale; v2 *= qscale; v3 *= qscale; }
                if (y == 3) {
                    float b0v = bg[col], b1v = bg[col + 1];
                    v0 = 1.0f / (1.0f + __expf(-(v0 + b0v)));
                    v1 = 1.0f / (1.0f + __expf(-(v1 + b1v)));
                    v2 = 1.0f / (1.0f + __expf(-(v2 + b0v)));
                    v3 = 1.0f / (1.0f + __expf(-(v3 + b1v)));
                }
                *(float2*)&O[(size_t)row0 * 128 + col]       = make_float2(v0, v1);
                *(float2*)&O[(size_t)(row0 + 8) * 128 + col] = make_float2(v2, v3);
            }
        }
    }
}

// ---------------- Kernel 3: tf32 MMA flash attention ---------------------
// block = (i,h), 384 threads = 12 warps, each warp owns 32 query rows.
#define KSTR 36   // Ksh row stride: conflict-free for S B-frags
#define VSTR 40   // Vsh row stride: conflict-free for PV B-frags

__global__ __launch_bounds__(384) void attn_kernel(const float* __restrict__ mask)
{
    extern __shared__ float sh[];
    float* Ksh = sh;                          // [384][KSTR], tf32 bits
    float* Vsh = sh + 384 * KSTR;             // [384][VSTR], tf32 bits
    float* mb  = sh + 384 * KSTR + 384 * VSTR;// [384], pre-scaled by LOG2E

    int i = blockIdx.x, h = blockIdx.y;
    int tid = threadIdx.x, wid = tid >> 5, lane = tid & 31;
    int q4 = lane & 3, r8 = lane >> 2;

    // stage K,V (tf32-converted)
    const float4* K4 = (const float4*)g_k + (size_t)i * J_DIM * 32 + h * 8;
    const float4* V4 = (const float4*)g_v + (size_t)i * J_DIM * 32 + h * 8;
    #pragma unroll
    for (int it = 0; it < 8; it++) {
        int idx = tid + it * 384;
        int j = idx >> 3, d4 = idx & 7;
        float4 kv = K4[(size_t)j * 32 + d4];
        float4 vv = V4[(size_t)j * 32 + d4];
        float4 kt = make_float4(tf2f(kv.x), tf2f(kv.y), tf2f(kv.z), tf2f(kv.w));
        float4 vt = make_float4(tf2f(vv.x), tf2f(vv.y), tf2f(vv.z), tf2f(vv.w));
        *(float4*)(Ksh + j * KSTR + d4 * 4) = kt;
        *(float4*)(Vsh + j * VSTR + d4 * 4) = vt;
    }
    mb[tid] = (LOG2E * 1.0e9f) * (mask[(size_t)i * J_DIM + tid] - 1.0f);
    __syncthreads();

    int qbase = wid * 32;
    // Q fragments (read once, tf32)
    uint32_t qa[2][4][4];
    #pragma unroll
    for (int mt = 0; mt < 2; mt++) {
        const float* Qp = g_q + ((size_t)i * J_DIM + qbase + mt * 16) * 128 + h * 32;
        #pragma unroll
        for (int ksp = 0; ksp < 4; ksp++) {
            const float* Qk = Qp + ksp * 8;
            qa[mt][ksp][0] = f2tf(Qk[r8 * 128 + q4]);
            qa[mt][ksp][1] = f2tf(Qk[(r8 + 8) * 128 + q4]);
            qa[mt][ksp][2] = f2tf(Qk[r8 * 128 + q4 + 4]);
            qa[mt][ksp][3] = f2tf(Qk[(r8 + 8) * 128 + q4 + 4]);
        }
    }

    float oacc[2][4][4];
    #pragma unroll
    for (int mt = 0; mt < 2; mt++)
        #pragma unroll
        for (int dn = 0; dn < 4; dn++)
            #pragma unroll
            for (int u = 0; u < 4; u++) oacc[mt][dn][u] = 0.0f;
    float mrow[2][2] = {{-1e30f, -1e30f}, {-1e30f, -1e30f}};
    float lrow[2][2] = {{0.0f, 0.0f}, {0.0f, 0.0f}};

    const float* triW = g_tri + (size_t)h * ROWS;
    int srcA = (lane & ~3) | (q4 >> 1);
    int srcB = srcA + 2;
    bool odd = (q4 & 1) != 0;

    #pragma unroll 1
    for (int kb = 0; kb < 12; kb++) {
        int kbase = kb * 32;

        // ---- S = Q K^T (32 keys) ----
        float sacc[2][4][4];
        #pragma unroll
        for (int mt = 0; mt < 2; mt++)
            #pragma unroll
            for (int nt = 0; nt < 4; nt++)
                #pragma unroll
                for (int u = 0; u < 4; u++) sacc[mt][nt][u] = 0.0f;

        #pragma unroll
        for (int nt = 0; nt < 4; nt++) {
            const float* Kp = Ksh + (kbase + nt * 8 + r8) * KSTR;
            #pragma unroll
            for (int ksp = 0; ksp < 4; ksp++) {
                uint32_t b0 = BITS(Kp[ksp * 8 + q4]);
                uint32_t b1 = BITS(Kp[ksp * 8 + q4 + 4]);
                mma8(sacc[0][nt], qa[0][ksp], b0, b1);
                mma8(sacc[1][nt], qa[1][ksp], b0, b1);
            }
        }

        // ---- bias + online softmax ----
        #pragma unroll
        for (int mt = 0; mt < 2; mt++) {
            int qrow = qbase + mt * 16 + r8;
            const float* t0p = triW + (size_t)qrow * J_DIM + kbase + 2 * q4;
            const float* t1p = t0p + 8 * J_DIM;
            float mx0 = -1e30f, mx1 = -1e30f;
            #pragma unroll
            for (int nt = 0; nt < 4; nt++) {
                float2 tA = *(const float2*)(t0p + nt * 8);
                float2 tB = *(const float2*)(t1p + nt * 8);
                float2 mv = *(const float2*)(mb + kbase + nt * 8 + 2 * q4);
                float* s = sacc[mt][nt];
                s[0] += tA.x + mv.x; s[1] += tA.y + mv.y;
                s[2] += tB.x + mv.x; s[3] += tB.y + mv.y;
                mx0 = fmaxf(mx0, fmaxf(s[0], s[1]));
                mx1 = fmaxf(mx1, fmaxf(s[2], s[3]));
            }
            mx0 = fmaxf(mx0, __shfl_xor_sync(~0u, mx0, 1));
            mx0 = fmaxf(mx0, __shfl_xor_sync(~0u, mx0, 2));
            mx1 = fmaxf(mx1, __shfl_xor_sync(~0u, mx1, 1));
            mx1 = fmaxf(mx1, __shfl_xor_sync(~0u, mx1, 2));
            float nm0 = fmaxf(mrow[mt][0], mx0);
            float nm1 = fmaxf(mrow[mt][1], mx1);
            float c0 = ex2(mrow[mt][0] - nm0);
            float c1 = ex2(mrow[mt][1] - nm1);
            mrow[mt][0] = nm0; mrow[mt][1] = nm1;
            float sum0 = 0.0f, sum1 = 0.0f;
            #pragma unroll
            for (int nt = 0; nt < 4; nt++) {
                float* s = sacc[mt][nt];
                s[0] = ex2(s[0] - nm0); s[1] = ex2(s[1] - nm0);
                s[2] = ex2(s[2] - nm1); s[3] = ex2(s[3] - nm1);
                sum0 += s[0] + s[1]; sum1 += s[2] + s[3];
            }
            sum0 += __shfl_xor_sync(~0u, sum0, 1);
            sum0 += __shfl_xor_sync(~0u, sum0, 2);
            sum1 += __shfl_xor_sync(~0u, sum1, 1);
            sum1 += __shfl_xor_sync(~0u, sum1, 2);
            lrow[mt][0] = lrow[mt][0] * c0 + sum0;
            lrow[mt][1] = lrow[mt][1] * c1 + sum1;
            #pragma unroll
            for (int dn = 0; dn < 4; dn++) {
                oacc[mt][dn][0] *= c0; oacc[mt][dn][1] *= c0;
                oacc[mt][dn][2] *= c1; oacc[mt][dn][3] *= c1;
            }
        }

        // ---- O += P V ----
        #pragma unroll
        for (int kc = 0; kc < 4; kc++) {
            uint32_t pa[2][4];
            #pragma unroll
            for (int mt = 0; mt < 2; mt++) {
                uint32_t t0 = f2tf(sacc[mt][kc][0]);
                uint32_t t1 = f2tf(sacc[mt][kc][1]);
                uint32_t t2 = f2tf(sacc[mt][kc][2]);
                uint32_t t3 = f2tf(sacc[mt][kc][3]);
                uint32_t e0 = __shfl_sync(~0u, t0, srcA), o0 = __shfl_sync(~0u, t1, srcA);
                uint32_t e1 = __shfl_sync(~0u, t2, srcA), o1 = __shfl_sync(~0u, t3, srcA);
                uint32_t e2 = __shfl_sync(~0u, t0, srcB), o2 = __shfl_sync(~0u, t1, srcB);
                uint32_t e3 = __shfl_sync(~0u, t2, srcB), o3 = __shfl_sync(~0u, t3, srcB);
                pa[mt][0] = odd ? o0 : e0;
                pa[mt][1] = odd ? o1 : e1;
                pa[mt][2] = odd ? o2 : e2;
                pa[mt][3] = odd ? o3 : e3;
            }
            int kk = kbase + kc * 8 + q4;
            #pragma unroll
            for (int dn = 0; dn < 4; dn++) {
                int dd = dn * 8 + r8;
                uint32_t b0 = BITS(Vsh[kk * VSTR + dd]);
                uint32_t b1 = BITS(Vsh[(kk + 4) * VSTR + dd]);
                mma8(oacc[0][dn], pa[0], b0, b1);
                mma8(oacc[1][dn], pa[1], b0, b1);
            }
        }
    }

    // ---- finalize: 1/l, gate, store ----
    #pragma unroll
    for (int mt = 0; mt < 2; mt++) {
        float inv0 = 1.0f / lrow[mt][0];
        float inv1 = 1.0f / lrow[mt][1];
        size_t row0 = ((size_t)i * J_DIM + qbase + mt * 16 + r8) * 128 + h * 32;
        size_t row1 = row0 + (size_t)8 * 128;
        #pragma unroll
        for (int dn = 0; dn < 4; dn++) {
            int c = dn * 8 + 2 * q4;
            float2 gv0 = *(const float2*)(g_g + row0 + c);
            float2 gv1 = *(const float2*)(g_g + row1 + c);
            *(float2*)(g_o + row0 + c) =
                make_float2(oacc[mt][dn][0] * inv0 * gv0.x,
                            oacc[mt][dn][1] * inv0 * gv0.y);
            *(float2*)(g_o + row1 + c) =
                make_float2(oacc[mt][dn][2] * inv1 * gv1.x,
                            oacc[mt][dn][3] * inv1 * gv1.y);
        }
    }
}

// ---------------- Kernel 4: output projection (scalar fp32, exact) -------
__global__ __launch_bounds__(256) void out_kernel(
    const float* __restrict__ wo, const float* __restrict__ bo,
    float* __restrict__ out)
{
    int m0 = blockIdx.x * 128;
    __shared__ float As[128 * 32];
    __shared__ float Bs[32 * 128];
    int tid = threadIdx.x;
    int ty = tid >> 4, tx = tid & 15;
    float acc[8][8];
    #pragma unroll
    for (int r = 0; r < 8; r++)
        #pragma unroll
        for (int j = 0; j < 8; j++) acc[r][j] = 0.0f;
    const float4* A4 = (const float4*)g_o;
    const float4* W4 = (const float4*)wo;
    for (int kt = 0; kt < 4; kt++) {
        #pragma unroll
        for (int i = 0; i < 4; i++) {
            int idx = tid + i * 256;
            int r = idx >> 3, kq = idx & 7;
            ((float4*)As)[idx] = A4[(size_t)(m0 + r) * 32 + kt * 8 + kq];
        }
        #pragma unroll
        for (int i = 0; i < 4; i++) {
            int idx = tid + i * 256;
            int k = idx >> 5, cq = idx & 31;
            ((float4*)Bs)[idx] = W4[(size_t)(kt * 32 + k) * 32 + cq];
        }
        __syncthreads();
        #pragma unroll
        for (int k = 0; k < 32; k++) {
            float a[8];
            #pragma unroll
            for (int r = 0; r < 8; r++) a[r] = As[(ty * 8 + r) * 32 + k];
            float4 b01 = *(const float4*)&Bs[k * 128 + tx * 8];
            float4 b23 = *(const float4*)&Bs[k * 128 + tx * 8 + 4];
            float b[8] = {b01.x, b01.y, b01.z, b01.w, b23.x, b23.y, b23.z, b23.w};
            #pragma unroll
            for (int r = 0; r < 8; r++)
                #pragma unroll
                for (int j = 0; j < 8; j++) acc[r][j] += a[r] * b[j];
        }
        __syncthreads();
    }
    #pragma unroll
    for (int r = 0; r < 8; r++) {
        float tmp[8];
        #pragma unroll
        for (int j = 0; j < 8; j++) tmp[j] = acc[r][j] + bo[tx * 8 + j];
        float4* orow = (float4*)&out[(size_t)(m0 + ty * 8 + r) * 128 + tx * 8];
        orow[0] = make_float4(tmp[0], tmp[1], tmp[2], tmp[3]);
        orow[1] = make_float4(tmp[4], tmp[5], tmp[6], tmp[7]);
    }
}

// ---------------- launch --------------------------------------------------
extern "C" void kernel_launch(void* const* d_in, const int* in_sizes, int n_in,
                              void* d_out, int out_size)
{
    const float* x     = (const float*)d_in[0];
    const float* mask  = (const float*)d_in[1];
    const float* ln_g  = (const float*)d_in[2];
    const float* ln_b  = (const float*)d_in[3];
    const float* w_tri = (const float*)d_in[4];
    const float* wq    = (const float*)d_in[5];
    const float* wk    = (const float*)d_in[6];
    const float* wv    = (const float*)d_in[7];
    const float* wg    = (const float*)d_in[8];
    const float* bg    = (const float*)d_in[9];
    const float* wo    = (const float*)d_in[10];
    const float* bo    = (const float*)d_in[11];
    float* out = (float*)d_out;

    const int SMEM_PROJ = (128 * SA + 128 * SB) * (int)sizeof(float);        // 137216
    const int SMEM_ATTN = (384 * KSTR + 384 * VSTR + 384) * (int)sizeof(float); // 118272
    cudaFuncSetAttribute(proj_kernel,
                         cudaFuncAttributeMaxDynamicSharedMemorySize, SMEM_PROJ);
    cudaFuncSetAttribute(attn_kernel,
                         cudaFuncAttributeMaxDynamicSharedMemorySize, SMEM_ATTN);

    ln_tri_kernel<<<ROWS / 8, 256>>>(x, ln_g, ln_b, w_tri);
    proj_kernel<<<ROWS / 128, 256, SMEM_PROJ>>>(wq, wk, wv, wg, bg);
    attn_kernel<<<dim3(I_DIM, H_DIM), 384, SMEM_ATTN>>>(mask);
    out_kernel<<<ROWS / 128, 256>>>(wo, bo, out);
}

// round 7
// speedup vs baseline: 4.7339x; 1.1316x over previous
#include <cuda_runtime.h>
#include <math.h>
#include <stdint.h>

#define I_DIM 384
#define J_DIM 384
#define C_DIM 128
#define H_DIM 4
#define ROWS (I_DIM * J_DIM)          // 147456
#define LN_EPS 1e-5f
#define LOG2E 1.4426950408889634f

// ---------------- scratch -----------------------------------------------
__device__ float g_xn[ROWS * C_DIM];
__device__ float g_tri[H_DIM * ROWS];   // [h][q*384+k], pre-scaled by LOG2E
__device__ float g_q[ROWS * C_DIM];     // pre-scaled by (1/sqrt(32))*LOG2E
__device__ float g_k[ROWS * C_DIM];
__device__ float g_v[ROWS * C_DIM];
__device__ float g_g[ROWS * C_DIM];
__device__ float g_o[ROWS * C_DIM];

// ---------------- helpers -----------------------------------------------
__device__ __forceinline__ uint32_t f2tf(float x) {
    uint32_t r; asm("cvt.rna.tf32.f32 %0, %1;" : "=r"(r) : "f"(x)); return r;
}
__device__ __forceinline__ float tf2f(float x) {
    return __uint_as_float(f2tf(x));
}
__device__ __forceinline__ float ex2(float x) {
    float r; asm("ex2.approx.ftz.f32 %0, %1;" : "=f"(r) : "f"(x)); return r;
}
__device__ __forceinline__ void mma8(float* c, const uint32_t* a,
                                     uint32_t b0, uint32_t b1) {
    asm volatile(
        "mma.sync.aligned.m16n8k8.row.col.f32.tf32.tf32.f32 "
        "{%0,%1,%2,%3},{%4,%5,%6,%7},{%8,%9},{%0,%1,%2,%3};"
        : "+f"(c[0]), "+f"(c[1]), "+f"(c[2]), "+f"(c[3])
        : "r"(a[0]), "r"(a[1]), "r"(a[2]), "r"(a[3]), "r"(b0), "r"(b1));
}
#define BITS(x) __float_as_uint(x)

// ---------------- Kernel 1: LN + tri (warp per row) ----------------------
__global__ __launch_bounds__(256) void ln_tri_kernel(
    const float* __restrict__ x, const float* __restrict__ ln_g,
    const float* __restrict__ ln_b, const float* __restrict__ w_tri)
{
    int row  = blockIdx.x * 8 + (threadIdx.x >> 5);
    int lane = threadIdx.x & 31;

    float4 v = ((const float4*)x)[(size_t)row * 32 + lane];
    float s = v.x + v.y + v.z + v.w;
    #pragma unroll
    for (int o = 16; o; o >>= 1) s += __shfl_xor_sync(~0u, s, o);
    float mean = s * (1.0f / 128.0f);

    float4 d = make_float4(v.x - mean, v.y - mean, v.z - mean, v.w - mean);
    float s2 = d.x*d.x + d.y*d.y + d.z*d.z + d.w*d.w;
    #pragma unroll
    for (int o = 16; o; o >>= 1) s2 += __shfl_xor_sync(~0u, s2, o);
    float rstd = rsqrtf(s2 * (1.0f / 128.0f) + LN_EPS);

    float4 gg = ((const float4*)ln_g)[lane];
    float4 bb = ((const float4*)ln_b)[lane];
    float4 xn;
    xn.x = d.x * rstd * gg.x + bb.x;
    xn.y = d.y * rstd * gg.y + bb.y;
    xn.z = d.z * rstd * gg.z + bb.z;
    xn.w = d.w * rstd * gg.w + bb.w;
    ((float4*)g_xn)[(size_t)row * 32 + lane] = xn;

    const float4* wt = (const float4*)w_tri;
    float4 w0 = wt[lane*4+0], w1 = wt[lane*4+1], w2 = wt[lane*4+2], w3 = wt[lane*4+3];
    float p0 = xn.x*w0.x + xn.y*w1.x + xn.z*w2.x + xn.w*w3.x;
    float p1 = xn.x*w0.y + xn.y*w1.y + xn.z*w2.y + xn.w*w3.y;
    float p2 = xn.x*w0.z + xn.y*w1.z + xn.z*w2.z + xn.w*w3.z;
    float p3 = xn.x*w0.w + xn.y*w1.w + xn.z*w2.w + xn.w*w3.w;
    #pragma unroll
    for (int o = 16; o; o >>= 1) {
        p0 += __shfl_xor_sync(~0u, p0, o);
        p1 += __shfl_xor_sync(~0u, p1, o);
        p2 += __shfl_xor_sync(~0u, p2, o);
        p3 += __shfl_xor_sync(~0u, p3, o);
    }
    if (lane < 4) {
        float pv = (lane == 0) ? p0 : (lane == 1) ? p1 : (lane == 2) ? p2 : p3;
        g_tri[(size_t)lane * ROWS + row] = pv * LOG2E;
    }
}

// ---------------- GEMM: 64x128 tile, 8 warps (2x4), warp tile 32x32 ------
#define SA 132    // (132 % 32 == 4) -> A frag banks 4*r8+q4, conflict-free
#define SB 136    // (136 % 32 == 8) -> B frag banks 8*q4+r8, conflict-free

#define MMA_MAINLOOP(ACC)                                              \
    _Pragma("unroll")                                                  \
    for (int ks = 0; ks < 16; ks++) {                                  \
        int k0 = ks * 8;                                               \
        uint32_t a[2][4];                                              \
        _Pragma("unroll")                                              \
        for (int mt = 0; mt < 2; mt++) {                               \
            int rb = warpM + mt * 16 + r8;                             \
            a[mt][0] = BITS(As[rb * SA + k0 + q4]);                    \
            a[mt][1] = BITS(As[(rb + 8) * SA + k0 + q4]);              \
            a[mt][2] = BITS(As[rb * SA + k0 + q4 + 4]);                \
            a[mt][3] = BITS(As[(rb + 8) * SA + k0 + q4 + 4]);          \
        }                                                              \
        _Pragma("unroll")                                              \
        for (int nt = 0; nt < 4; nt++) {                               \
            int nb = warpN + nt * 8 + r8;                              \
            uint32_t b0 = BITS(Bs[(k0 + q4) * SB + nb]);               \
            uint32_t b1 = BITS(Bs[(k0 + q4 + 4) * SB + nb]);           \
            mma8(ACC[0][nt], a[0], b0, b1);                            \
            mma8(ACC[1][nt], a[1], b0, b1);                            \
        }                                                              \
    }

// ---------------- Kernel 2: fused q/k/v/g projection ---------------------
__global__ __launch_bounds__(256, 2) void proj_kernel(
    const float* __restrict__ wq, const float* __restrict__ wk,
    const float* __restrict__ wv, const float* __restrict__ wg,
    const float* __restrict__ bg)
{
    extern __shared__ float sh[];
    float* As = sh;                 // [64][SA]
    float* Bs = sh + 64 * SA;       // [128][SB]

    int m0 = blockIdx.x * 64;
    int tid = threadIdx.x, wid = tid >> 5, lane = tid & 31;
    int warpM = (wid >> 2) * 32, warpN = (wid & 3) * 32;
    int q4 = lane & 3, r8 = lane >> 2;

    const float4* A4 = (const float4*)g_xn + (size_t)m0 * 32;
    #pragma unroll
    for (int it = 0; it < 8; it++) {
        int idx = tid + it * 256;       // 0..2047
        int rr = idx >> 5, c4 = idx & 31;
        float4 v = A4[rr * 32 + c4];
        float* dst = As + rr * SA + c4 * 4;
        dst[0] = tf2f(v.x); dst[1] = tf2f(v.y); dst[2] = tf2f(v.z); dst[3] = tf2f(v.w);
    }

    #pragma unroll 1
    for (int y = 0; y < 4; y++) {
        const float* W = (y == 0) ? wq : (y == 1) ? wk : (y == 2) ? wv : wg;
        float*       O = (y == 0) ? g_q : (y == 1) ? g_k : (y == 2) ? g_v : g_g;

        __syncthreads();          // A staged (y=0) / prior readers done
        const float4* W4 = (const float4*)W;
        #pragma unroll
        for (int it = 0; it < 16; it++) {
            int idx = tid + it * 256;   // 0..4095
            int kk = idx >> 5, c4 = idx & 31;
            float4 v = W4[idx];
            float* dst = Bs + kk * SB + c4 * 4;
            dst[0] = tf2f(v.x); dst[1] = tf2f(v.y); dst[2] = tf2f(v.z); dst[3] = tf2f(v.w);
        }
        __syncthreads();

        float acc[2][4][4];
        #pragma unroll
        for (int mt = 0; mt < 2; mt++)
            #pragma unroll
            for (int nt = 0; nt < 4; nt++)
                #pragma unroll
                for (int u = 0; u < 4; u++) acc[mt][nt][u] = 0.0f;

        MMA_MAINLOOP(acc)

        const float qscale = 0.17677669529663687f * LOG2E;
        #pragma unroll
        for (int mt = 0; mt < 2; mt++) {
            int row0 = m0 + warpM + mt * 16 + r8;
            #pragma unroll
            for (int nt = 0; nt < 4; nt++) {
                int col = warpN + nt * 8 + 2 * q4;
                float v0 = acc[mt][nt][0], v1 = acc[mt][nt][1];
                float v2 = acc[mt][nt][2], v3 = acc[mt][nt][3];
                if (y == 0) { v0 *= qscale; v1 *= qscale; v2 *= qscale; v3 *= qscale; }
                if (y == 3) {
                    float b0v = bg[col], b1v = bg[col + 1];
                    v0 = 1.0f / (1.0f + __expf(-(v0 + b0v)));
                    v1 = 1.0f / (1.0f + __expf(-(v1 + b1v)));
                    v2 = 1.0f / (1.0f + __expf(-(v2 + b0v)));
                    v3 = 1.0f / (1.0f + __expf(-(v3 + b1v)));
                }
                *(float2*)&O[(size_t)row0 * 128 + col]       = make_float2(v0, v1);
                *(float2*)&O[(size_t)(row0 + 8) * 128 + col] = make_float2(v2, v3);
            }
        }
    }
}

// ---------------- Kernel 3: tf32 MMA flash attention ---------------------
// block = (i,h), 768 threads = 24 warps, each warp owns 16 query rows.
#define KSTR 36
#define VSTR 40

__global__ __launch_bounds__(768) void attn_kernel(const float* __restrict__ mask)
{
    extern __shared__ float sh[];
    float* Ksh = sh;                          // [384][KSTR]
    float* Vsh = sh + 384 * KSTR;             // [384][VSTR]
    float* mb  = sh + 384 * KSTR + 384 * VSTR;// [384]

    int i = blockIdx.x, h = blockIdx.y;
    int tid = threadIdx.x, wid = tid >> 5, lane = tid & 31;
    int q4 = lane & 3, r8 = lane >> 2;

    const float4* K4 = (const float4*)g_k + (size_t)i * J_DIM * 32 + h * 8;
    const float4* V4 = (const float4*)g_v + (size_t)i * J_DIM * 32 + h * 8;
    #pragma unroll
    for (int it = 0; it < 4; it++) {
        int idx = tid + it * 768;           // 0..3071
        int j = idx >> 3, d4 = idx & 7;
        float4 kv = K4[(size_t)j * 32 + d4];
        float4 vv = V4[(size_t)j * 32 + d4];
        float4 kt = make_float4(tf2f(kv.x), tf2f(kv.y), tf2f(kv.z), tf2f(kv.w));
        float4 vt = make_float4(tf2f(vv.x), tf2f(vv.y), tf2f(vv.z), tf2f(vv.w));
        *(float4*)(Ksh + j * KSTR + d4 * 4) = kt;
        *(float4*)(Vsh + j * VSTR + d4 * 4) = vt;
    }
    if (tid < 384)
        mb[tid] = (LOG2E * 1.0e9f) * (mask[(size_t)i * J_DIM + tid] - 1.0f);
    __syncthreads();

    int qbase = wid * 16;
    uint32_t qa[4][4];
    {
        const float* Qp = g_q + ((size_t)i * J_DIM + qbase) * 128 + h * 32;
        #pragma unroll
        for (int ksp = 0; ksp < 4; ksp++) {
            const float* Qk = Qp + ksp * 8;
            qa[ksp][0] = f2tf(Qk[r8 * 128 + q4]);
            qa[ksp][1] = f2tf(Qk[(r8 + 8) * 128 + q4]);
            qa[ksp][2] = f2tf(Qk[r8 * 128 + q4 + 4]);
            qa[ksp][3] = f2tf(Qk[(r8 + 8) * 128 + q4 + 4]);
        }
    }

    float oacc[4][4];
    #pragma unroll
    for (int dn = 0; dn < 4; dn++)
        #pragma unroll
        for (int u = 0; u < 4; u++) oacc[dn][u] = 0.0f;
    float mrow0 = -1e30f, mrow1 = -1e30f, lrow0 = 0.0f, lrow1 = 0.0f;

    const float* triW = g_tri + (size_t)h * ROWS;
    int srcA = (lane & ~3) | (q4 >> 1);
    int srcB = srcA + 2;
    bool odd = (q4 & 1) != 0;

    #pragma unroll 1
    for (int kb = 0; kb < 12; kb++) {
        int kbase = kb * 32;

        // ---- S = Q K^T (16 rows x 32 keys) ----
        float sacc[4][4];
        #pragma unroll
        for (int nt = 0; nt < 4; nt++)
            #pragma unroll
            for (int u = 0; u < 4; u++) sacc[nt][u] = 0.0f;

        #pragma unroll
        for (int nt = 0; nt < 4; nt++) {
            const float* Kp = Ksh + (kbase + nt * 8 + r8) * KSTR;
            #pragma unroll
            for (int ksp = 0; ksp < 4; ksp++) {
                uint32_t b0 = BITS(Kp[ksp * 8 + q4]);
                uint32_t b1 = BITS(Kp[ksp * 8 + q4 + 4]);
                mma8(sacc[nt], qa[ksp], b0, b1);
            }
        }

        // ---- bias + online softmax ----
        {
            int qrow = qbase + r8;
            const float* t0p = triW + (size_t)qrow * J_DIM + kbase + 2 * q4;
            const float* t1p = t0p + 8 * J_DIM;
            float mx0 = -1e30f, mx1 = -1e30f;
            #pragma unroll
            for (int nt = 0; nt < 4; nt++) {
                float2 tA = *(const float2*)(t0p + nt * 8);
                float2 tB = *(const float2*)(t1p + nt * 8);
                float2 mv = *(const float2*)(mb + kbase + nt * 8 + 2 * q4);
                float* s = sacc[nt];
                s[0] += tA.x + mv.x; s[1] += tA.y + mv.y;
                s[2] += tB.x + mv.x; s[3] += tB.y + mv.y;
                mx0 = fmaxf(mx0, fmaxf(s[0], s[1]));
                mx1 = fmaxf(mx1, fmaxf(s[2], s[3]));
            }
            mx0 = fmaxf(mx0, __shfl_xor_sync(~0u, mx0, 1));
            mx0 = fmaxf(mx0, __shfl_xor_sync(~0u, mx0, 2));
            mx1 = fmaxf(mx1, __shfl_xor_sync(~0u, mx1, 1));
            mx1 = fmaxf(mx1, __shfl_xor_sync(~0u, mx1, 2));
            float nm0 = fmaxf(mrow0, mx0);
            float nm1 = fmaxf(mrow1, mx1);
            float c0 = ex2(mrow0 - nm0);
            float c1 = ex2(mrow1 - nm1);
            mrow0 = nm0; mrow1 = nm1;
            float sum0 = 0.0f, sum1 = 0.0f;
            #pragma unroll
            for (int nt = 0; nt < 4; nt++) {
                float* s = sacc[nt];
                s[0] = ex2(s[0] - nm0); s[1] = ex2(s[1] - nm0);
                s[2] = ex2(s[2] - nm1); s[3] = ex2(s[3] - nm1);
                sum0 += s[0] + s[1]; sum1 += s[2] + s[3];
            }
            sum0 += __shfl_xor_sync(~0u, sum0, 1);
            sum0 += __shfl_xor_sync(~0u, sum0, 2);
            sum1 += __shfl_xor_sync(~0u, sum1, 1);
            sum1 += __shfl_xor_sync(~0u, sum1, 2);
            lrow0 = lrow0 * c0 + sum0;
            lrow1 = lrow1 * c1 + sum1;
            #pragma unroll
            for (int dn = 0; dn < 4; dn++) {
                oacc[dn][0] *= c0; oacc[dn][1] *= c0;
                oacc[dn][2] *= c1; oacc[dn][3] *= c1;
            }
        }

        // ---- O += P V ----
        #pragma unroll
        for (int kc = 0; kc < 4; kc++) {
            uint32_t pa[4];
            {
                uint32_t t0 = f2tf(sacc[kc][0]);
                uint32_t t1 = f2tf(sacc[kc][1]);
                uint32_t t2 = f2tf(sacc[kc][2]);
                uint32_t t3 = f2tf(sacc[kc][3]);
                uint32_t e0 = __shfl_sync(~0u, t0, srcA), o0 = __shfl_sync(~0u, t1, srcA);
                uint32_t e1 = __shfl_sync(~0u, t2, srcA), o1 = __shfl_sync(~0u, t3, srcA);
                uint32_t e2 = __shfl_sync(~0u, t0, srcB), o2 = __shfl_sync(~0u, t1, srcB);
                uint32_t e3 = __shfl_sync(~0u, t2, srcB), o3 = __shfl_sync(~0u, t3, srcB);
                pa[0] = odd ? o0 : e0;
                pa[1] = odd ? o1 : e1;
                pa[2] = odd ? o2 : e2;
                pa[3] = odd ? o3 : e3;
            }
            int kk = kbase + kc * 8 + q4;
            #pragma unroll
            for (int dn = 0; dn < 4; dn++) {
                int dd = dn * 8 + r8;
                uint32_t b0 = BITS(Vsh[kk * VSTR + dd]);
                uint32_t b1 = BITS(Vsh[(kk + 4) * VSTR + dd]);
                mma8(oacc[dn], pa, b0, b1);
            }
        }
    }

    // ---- finalize: 1/l, gate, store ----
    {
        float inv0 = 1.0f / lrow0;
        float inv1 = 1.0f / lrow1;
        size_t row0 = ((size_t)i * J_DIM + qbase + r8) * 128 + h * 32;
        size_t row1 = row0 + (size_t)8 * 128;
        #pragma unroll
        for (int dn = 0; dn < 4; dn++) {
            int c = dn * 8 + 2 * q4;
            float2 gv0 = *(const float2*)(g_g + row0 + c);
            float2 gv1 = *(const float2*)(g_g + row1 + c);
            *(float2*)(g_o + row0 + c) =
                make_float2(oacc[dn][0] * inv0 * gv0.x,
                            oacc[dn][1] * inv0 * gv0.y);
            *(float2*)(g_o + row1 + c) =
                make_float2(oacc[dn][2] * inv1 * gv1.x,
                            oacc[dn][3] * inv1 * gv1.y);
        }
    }
}

// ---------------- Kernel 4: output projection (tf32 MMA) ------------------
__global__ __launch_bounds__(256, 2) void out_kernel(
    const float* __restrict__ wo, const float* __restrict__ bo,
    float* __restrict__ out)
{
    extern __shared__ float sh[];
    float* As = sh;                 // [64][SA]
    float* Bs = sh + 64 * SA;       // [128][SB]

    int m0 = blockIdx.x * 64;
    int tid = threadIdx.x, wid = tid >> 5, lane = tid & 31;
    int warpM = (wid >> 2) * 32, warpN = (wid & 3) * 32;
    int q4 = lane & 3, r8 = lane >> 2;

    const float4* A4 = (const float4*)g_o + (size_t)m0 * 32;
    #pragma unroll
    for (int it = 0; it < 8; it++) {
        int idx = tid + it * 256;
        int rr = idx >> 5, c4 = idx & 31;
        float4 v = A4[rr * 32 + c4];
        float* dst = As + rr * SA + c4 * 4;
        dst[0] = tf2f(v.x); dst[1] = tf2f(v.y); dst[2] = tf2f(v.z); dst[3] = tf2f(v.w);
    }
    const float4* W4 = (const float4*)wo;
    #pragma unroll
    for (int it = 0; it < 16; it++) {
        int idx = tid + it * 256;
        int kk = idx >> 5, c4 = idx & 31;
        float4 v = W4[idx];
        float* dst = Bs + kk * SB + c4 * 4;
        dst[0] = tf2f(v.x); dst[1] = tf2f(v.y); dst[2] = tf2f(v.z); dst[3] = tf2f(v.w);
    }
    __syncthreads();

    float acc[2][4][4];
    #pragma unroll
    for (int mt = 0; mt < 2; mt++)
        #pragma unroll
        for (int nt = 0; nt < 4; nt++)
            #pragma unroll
            for (int u = 0; u < 4; u++) acc[mt][nt][u] = 0.0f;

    MMA_MAINLOOP(acc)

    #pragma unroll
    for (int mt = 0; mt < 2; mt++) {
        int row0 = m0 + warpM + mt * 16 + r8;
        #pragma unroll
        for (int nt = 0; nt < 4; nt++) {
            int col = warpN + nt * 8 + 2 * q4;
            float b0v = bo[col], b1v = bo[col + 1];
            *(float2*)&out[(size_t)row0 * 128 + col] =
                make_float2(acc[mt][nt][0] + b0v, acc[mt][nt][1] + b1v);
            *(float2*)&out[(size_t)(row0 + 8) * 128 + col] =
                make_float2(acc[mt][nt][2] + b0v, acc[mt][nt][3] + b1v);
        }
    }
}

// ---------------- launch --------------------------------------------------
extern "C" void kernel_launch(void* const* d_in, const int* in_sizes, int n_in,
                              void* d_out, int out_size)
{
    const float* x     = (const float*)d_in[0];
    const float* mask  = (const float*)d_in[1];
    const float* ln_g  = (const float*)d_in[2];
    const float* ln_b  = (const float*)d_in[3];
    const float* w_tri = (const float*)d_in[4];
    const float* wq    = (const float*)d_in[5];
    const float* wk    = (const float*)d_in[6];
    const float* wv    = (const float*)d_in[7];
    const float* wg    = (const float*)d_in[8];
    const float* bg    = (const float*)d_in[9];
    const float* wo    = (const float*)d_in[10];
    const float* bo    = (const float*)d_in[11];
    float* out = (float*)d_out;

    const int SMEM_GEMM = (64 * SA + 128 * SB) * (int)sizeof(float);           // 103424
    const int SMEM_ATTN = (384 * KSTR + 384 * VSTR + 384) * (int)sizeof(float); // 118272
    cudaFuncSetAttribute(proj_kernel,
                         cudaFuncAttributeMaxDynamicSharedMemorySize, SMEM_GEMM);
    cudaFuncSetAttribute(out_kernel,
                         cudaFuncAttributeMaxDynamicSharedMemorySize, SMEM_GEMM);
    cudaFuncSetAttribute(attn_kernel,
                         cudaFuncAttributeMaxDynamicSharedMemorySize, SMEM_ATTN);

    ln_tri_kernel<<<ROWS / 8, 256>>>(x, ln_g, ln_b, w_tri);
    proj_kernel<<<ROWS / 64, 256, SMEM_GEMM>>>(wq, wk, wv, wg, bg);
    attn_kernel<<<dim3(I_DIM, H_DIM), 768, SMEM_ATTN>>>(mask);
    out_kernel<<<ROWS / 64, 256, SMEM_GEMM>>>(wo, bo, out);
}